// round 11
// baseline (speedup 1.0000x reference)
#include <cuda_runtime.h>
#include <math.h>
#include <stdint.h>

// Problem constants
#define B 64
#define S 512
#define D 1024
#define H 1024
#define G 4096  // 4*H

// Persistent step kernel: 128 CTAs x 1024 threads (32 warps, split-k by 4)
#define NCTA 128
#define THREADS 1024
// Weight slab per CTA: 128 ksteps * 2 mblk * 32 lanes * 16B = 8192 uint4 = 128KB
#define W_SLAB_UINT4 8192
#define SG_STRIDE 66
#define DYN_SMEM_BYTES (W_SLAB_UINT4 * 16 + 4 * 32 * SG_STRIDE * 4)  // 164864

// xproj tensor-core GEMM geometry
#define XP_BM 128
#define XP_BN 128
#define XP_NMT (B * S / XP_BM)   // 256 m-tiles
#define XP_NNT (G / XP_BN)       // 32 n-tiles
#define XP_CHUNK_U4 1024         // one BK=32 chunk = 16KB
#define XP_SMEM_BYTES (4 * XP_CHUNK_U4 * 16)  // 64KB

// Device scratch (no allocation allowed)
__device__ float    g_xproj[(size_t)B * S * G];                  // [B*S, 4H]
__device__ uint32_t g_wpack[(size_t)NCTA * W_SLAB_UINT4 * 4];    // Whh tf32, fragment-packed
__device__ uint32_t g_hpack[2][128 * 4 * 32 * 4];                // h tf32, fragment-packed (ping-pong)
__device__ float    g_c[B * H];                                  // cell state (start/end only)
__device__ unsigned g_bar;                                       // global step barrier
__device__ uint32_t g_xpack[(size_t)XP_NMT * 128 * 8 * 32 * 4];  // inputs tf32 A-frag-packed
__device__ uint32_t g_wihpack[(size_t)XP_NNT * 128 * 8 * 32 * 4]; // Wih tf32 B-frag-packed

// ---------------------------------------------------------------------------
// Helpers
// ---------------------------------------------------------------------------
__device__ __forceinline__ uint32_t smem_u32(const void* p) {
    uint32_t a;
    asm("{ .reg .u64 t; cvta.to.shared.u64 t, %1; cvt.u32.u64 %0, t; }"
        : "=r"(a) : "l"(p));
    return a;
}

__device__ __forceinline__ uint32_t f2tf32(float f) {
    uint32_t r;
    asm("cvt.rna.tf32.f32 %0, %1;" : "=r"(r) : "f"(f));
    return r;
}

#define CP_ASYNC16(dst, src) \
    asm volatile("cp.async.cg.shared.global [%0], [%1], 16;" :: "r"(dst), "l"(src) : "memory")
#define CP_COMMIT() asm volatile("cp.async.commit_group;" ::: "memory")
#define CP_WAIT(n)  asm volatile("cp.async.wait_group %0;" :: "n"(n) : "memory")

#define MMA_TF32(c0, c1, c2, c3, a0, a1, a2, a3, b0, b1)                     \
    asm volatile("mma.sync.aligned.m16n8k8.row.col.f32.tf32.tf32.f32 "       \
                 "{%0,%1,%2,%3}, {%4,%5,%6,%7}, {%8,%9}, {%0,%1,%2,%3};"     \
                 : "+f"(c0), "+f"(c1), "+f"(c2), "+f"(c3)                    \
                 : "r"(a0), "r"(a1), "r"(a2), "r"(a3), "r"(b0), "r"(b1))

// ---------------------------------------------------------------------------
// Whh prep: tf32 per-lane A-fragment order for the step kernel.
// ---------------------------------------------------------------------------
__global__ void prep_wpack(const float* __restrict__ whh) {
    int idx = blockIdx.x * 256 + threadIdx.x;   // 0 .. 4M-1
    int a     = idx & 3;
    int lane  = (idx >> 2) & 31;
    int mblk  = (idx >> 7) & 1;
    int kstep = (idx >> 8) & 127;
    int ct    = idx >> 15;

    int row16 = (lane >> 2) + 8 * (a & 1);
    int kofs  = (lane & 3) + 4 * (a >> 1);
    int r = mblk * 16 + row16;
    int q = r >> 3;
    int j = r & 7;
    int grow = q * H + ct * 8 + j;
    int k = kstep * 8 + kofs;
    g_wpack[idx] = f2tf32(whh[(size_t)grow * H + k]);
}

// ---------------------------------------------------------------------------
// xproj A-pack: inputs [B*S, D] fp32 -> tf32 A-fragment order.
// ---------------------------------------------------------------------------
__global__ void prep_xpack(const float* __restrict__ inp) {
    int idx = blockIdx.x * 256 + threadIdx.x;   // 0 .. 32M-1
    int a     = idx & 3;
    int lane  = (idx >> 2) & 31;
    int mblk  = (idx >> 7) & 7;
    int kstep = (idx >> 10) & 127;
    int mtile = idx >> 17;

    int m = mtile * 128 + mblk * 16 + (lane >> 2) + 8 * (a & 1);
    int k = kstep * 8 + (lane & 3) + 4 * (a >> 1);
    g_xpack[idx] = f2tf32(inp[(size_t)m * D + k]);
}

// ---------------------------------------------------------------------------
// xproj B-pack: Wih [G, D] fp32 -> tf32 B-fragment order (paired n8 blocks).
// ---------------------------------------------------------------------------
__global__ void prep_wihpack(const float* __restrict__ wih) {
    int idx = blockIdx.x * 256 + threadIdx.x;   // 0 .. 4M-1
    int w     = idx & 3;
    int lane  = (idx >> 2) & 31;
    int npair = (idx >> 7) & 7;
    int kstep = (idx >> 10) & 127;
    int ntile = idx >> 17;

    int nsub = w >> 1, bsel = w & 1;
    int n = ntile * 128 + npair * 16 + nsub * 8 + (lane >> 2);
    int k = kstep * 8 + (lane & 3) + 4 * bsel;
    g_wihpack[idx] = f2tf32(wih[(size_t)n * D + k]);
}

// ---------------------------------------------------------------------------
// hpack addressing
// ---------------------------------------------------------------------------
__device__ __forceinline__ uint32_t hpack_addr(int b, int hid) {
    int kstep = hid >> 3, kk = hid & 7;
    int khalf = kk >> 2, kfrac = kk & 3;
    int nblk = b >> 4, rem = b & 15;
    int jb = rem >> 3, trow = rem & 7;
    int lane = trow * 4 + kfrac;
    int f = khalf * 2 + jb;
    return (uint32_t)(((kstep * 4 + nblk) * 32 + lane) * 4 + f);
}

__global__ void init_state(const float* __restrict__ h0,
                           const float* __restrict__ c0) {
    int i = blockIdx.x * blockDim.x + threadIdx.x;
    if (i == 0) g_bar = 0u;
    if (i < B * H) {
        g_c[i] = c0[i];
        int b = i >> 10, hid = i & 1023;
        g_hpack[0][hpack_addr(b, hid)] = f2tf32(h0[i]);
    }
}

// ---------------------------------------------------------------------------
// xproj GEMM on tensor cores (unchanged from round 7)
// ---------------------------------------------------------------------------
__global__ void __launch_bounds__(256, 2)
xproj_mma(const float* __restrict__ bias) {
    extern __shared__ __align__(16) uint4 xsm[];
    uint32_t aAddr[2] = { smem_u32(xsm), smem_u32(xsm + XP_CHUNK_U4) };
    uint32_t bAddr[2] = { smem_u32(xsm + 2 * XP_CHUNK_U4), smem_u32(xsm + 3 * XP_CHUNK_U4) };

    int tid = threadIdx.x;
    int wid = tid >> 5;
    int lane = tid & 31;
    int wm = wid & 1;
    int wn = wid >> 1;
    int mtile = blockIdx.y;
    int ntile = blockIdx.x;

    const uint4* gA = (const uint4*)g_xpack + (size_t)mtile * (128 * 8 * 32);
    const uint4* gB = (const uint4*)g_wihpack + (size_t)ntile * (128 * 8 * 32);

    float acc[4][4][4] = {};

#pragma unroll
    for (int i = 0; i < 4; i++) {
        int l = tid + i * 256;
        CP_ASYNC16(aAddr[0] + l * 16, (const char*)gA + l * 16);
        CP_ASYNC16(bAddr[0] + l * 16, (const char*)gB + l * 16);
    }
    CP_COMMIT();

    for (int ki = 0; ki < 32; ki++) {
        if (ki + 1 < 32) {
            int nb = (ki + 1) & 1;
            const char* srcA = (const char*)(gA + (size_t)(ki + 1) * XP_CHUNK_U4);
            const char* srcB = (const char*)(gB + (size_t)(ki + 1) * XP_CHUNK_U4);
#pragma unroll
            for (int i = 0; i < 4; i++) {
                int l = tid + i * 256;
                CP_ASYNC16(aAddr[nb] + l * 16, srcA + l * 16);
                CP_ASYNC16(bAddr[nb] + l * 16, srcB + l * 16);
            }
            CP_COMMIT();
            CP_WAIT(1);
        } else {
            CP_WAIT(0);
        }
        __syncthreads();

        const uint4* cA = xsm + (ki & 1) * XP_CHUNK_U4;
        const uint4* cB = xsm + (2 + (ki & 1)) * XP_CHUNK_U4;
#pragma unroll
        for (int ks = 0; ks < 4; ks++) {
            uint4 av[4], bv[2];
#pragma unroll
            for (int m = 0; m < 4; m++)
                av[m] = cA[ks * 256 + (wm * 4 + m) * 32 + lane];
#pragma unroll
            for (int p = 0; p < 2; p++)
                bv[p] = cB[ks * 256 + (wn * 2 + p) * 32 + lane];
#pragma unroll
            for (int m = 0; m < 4; m++) {
                MMA_TF32(acc[m][0][0], acc[m][0][1], acc[m][0][2], acc[m][0][3],
                         av[m].x, av[m].y, av[m].z, av[m].w, bv[0].x, bv[0].y);
                MMA_TF32(acc[m][1][0], acc[m][1][1], acc[m][1][2], acc[m][1][3],
                         av[m].x, av[m].y, av[m].z, av[m].w, bv[0].z, bv[0].w);
                MMA_TF32(acc[m][2][0], acc[m][2][1], acc[m][2][2], acc[m][2][3],
                         av[m].x, av[m].y, av[m].z, av[m].w, bv[1].x, bv[1].y);
                MMA_TF32(acc[m][3][0], acc[m][3][1], acc[m][3][2], acc[m][3][3],
                         av[m].x, av[m].y, av[m].z, av[m].w, bv[1].z, bv[1].w);
            }
        }
        __syncthreads();
    }

#pragma unroll
    for (int m = 0; m < 4; m++) {
        int row = mtile * 128 + wm * 64 + m * 16 + (lane >> 2);
#pragma unroll
        for (int j = 0; j < 4; j++) {
            int col = ntile * 128 + wn * 32 + j * 8 + (lane & 3) * 2;
            float b0 = bias[col], b1 = bias[col + 1];
            *(float2*)&g_xproj[(size_t)row * G + col] =
                make_float2(acc[m][j][0] + b0, acc[m][j][1] + b1);
            *(float2*)&g_xproj[(size_t)(row + 8) * G + col] =
                make_float2(acc[m][j][2] + b0, acc[m][j][3] + b1);
        }
    }
}

// ---------------------------------------------------------------------------
// Persistent LSTM. Round-11 change vs R10: 1024 threads / 32 warps with
// split-k by 4. Warp w: kquarter = w>>3 handles 32 of 128 ksteps; partials
// in 4 sG planes; pointwise (threads 0-511) sums all 4. 8 warps/SMSP; serial
// MMA chains 64 -> 32; prefetch depth reduced to 2 (reg budget at 1024 thr).
// ---------------------------------------------------------------------------
__global__ void __launch_bounds__(THREADS, 1)
lstm_persist(const float* __restrict__ bias_hh, float* __restrict__ out) {
    extern __shared__ __align__(16) uint4 smem4[];
    uint4* sW = smem4;                              // 8192 uint4 weight slab
    float* sG = (float*)(smem4 + W_SLAB_UINT4);     // [4][32][SG_STRIDE]

    int tid = threadIdx.x;
    int wid = tid >> 5;
    int lane = tid & 31;
    int bx = blockIdx.x;
    int kq = wid >> 3;             // k-quarter 0..3
    int sub = wid & 7;
    int mblk = sub & 1;
    int nblk = sub >> 1;

    const uint4* gW = (const uint4*)g_wpack + (size_t)bx * W_SLAB_UINT4;
#pragma unroll
    for (int i = 0; i < W_SLAB_UINT4 / THREADS; i++)
        sW[tid + i * THREADS] = gW[tid + i * THREADS];

    // Pointwise mapping: threads 0-511 own (b = tid>>3, hid)
    int j = tid & 7;
    int b0 = tid >> 3;             // 0..127 (valid < 64)
    int hid = bx * 8 + j;
    bool pw = (tid < 512);
    float bi0 = 0.f, bi1 = 0.f, bi2 = 0.f, bi3 = 0.f, creg = 0.f;
    if (pw) {
        bi0 = bias_hh[hid];
        bi1 = bias_hh[H + hid];
        bi2 = bias_hh[2 * H + hid];
        bi3 = bias_hh[3 * H + hid];
        creg = g_c[b0 * H + hid];
    }

    __syncthreads();

    int bIdx = nblk * 32 + lane;
    int aBase = mblk * 32 + lane;
    int kbase = kq * 32;
    unsigned* barp = &g_bar;

    // Prefetch xproj for t=0
    float xp[4] = {0.f, 0.f, 0.f, 0.f};
    if (pw) {
        size_t xb = (size_t)b0 * S * G + hid;
        xp[0] = __ldg(&g_xproj[xb]);
        xp[1] = __ldg(&g_xproj[xb + H]);
        xp[2] = __ldg(&g_xproj[xb + 2 * H]);
        xp[3] = __ldg(&g_xproj[xb + 3 * H]);
    }

    for (int t = 0; t < S; t++) {
        const uint4* gB4 = (const uint4*)g_hpack[t & 1];

        float c00 = 0.f, c01 = 0.f, c02 = 0.f, c03 = 0.f;
        float c10 = 0.f, c11 = 0.f, c12 = 0.f, c13 = 0.f;

        uint4 bvA[2], bvB[2];
#pragma unroll
        for (int k = 0; k < 2; k++)
            bvA[k] = __ldcg(&gB4[(kbase + k) * 128 + bIdx]);

#pragma unroll 1
        for (int ks0 = 0; ks0 < 32; ks0 += 4) {
#pragma unroll
            for (int k = 0; k < 2; k++)
                bvB[k] = __ldcg(&gB4[(kbase + ks0 + 2 + k) * 128 + bIdx]);
#pragma unroll
            for (int k = 0; k < 2; k++) {
                uint4 av = sW[(kbase + ks0 + k) * 64 + aBase];
                MMA_TF32(c00, c01, c02, c03, av.x, av.y, av.z, av.w, bvA[k].x, bvA[k].z);
                MMA_TF32(c10, c11, c12, c13, av.x, av.y, av.z, av.w, bvA[k].y, bvA[k].w);
            }
            if (ks0 + 4 < 32) {
#pragma unroll
                for (int k = 0; k < 2; k++)
                    bvA[k] = __ldcg(&gB4[(kbase + ks0 + 4 + k) * 128 + bIdx]);
            }
#pragma unroll
            for (int k = 0; k < 2; k++) {
                uint4 av = sW[(kbase + ks0 + 2 + k) * 64 + aBase];
                MMA_TF32(c00, c01, c02, c03, av.x, av.y, av.z, av.w, bvB[k].x, bvB[k].z);
                MMA_TF32(c10, c11, c12, c13, av.x, av.y, av.z, av.w, bvB[k].y, bvB[k].w);
            }
        }

        // Exchange: warp writes its partial C into its k-quarter plane
        {
            float* sGp = sG + kq * 32 * SG_STRIDE;
            int r0 = mblk * 16 + (lane >> 2);
            int col = nblk * 16 + (lane & 3) * 2;
            *(float2*)&sGp[r0 * SG_STRIDE + col]           = make_float2(c00, c01);
            *(float2*)&sGp[(r0 + 8) * SG_STRIDE + col]     = make_float2(c02, c03);
            *(float2*)&sGp[r0 * SG_STRIDE + col + 8]       = make_float2(c10, c11);
            *(float2*)&sGp[(r0 + 8) * SG_STRIDE + col + 8] = make_float2(c12, c13);
        }
        __syncthreads();

        uint32_t* hnext = g_hpack[(t + 1) & 1];
        if (pw) {
            const float* p0 = sG;
            const float* p1 = sG + 1 * 32 * SG_STRIDE;
            const float* p2 = sG + 2 * 32 * SG_STRIDE;
            const float* p3 = sG + 3 * 32 * SG_STRIDE;
            int o0 = (0 * 8 + j) * SG_STRIDE + b0;
            int o1 = (1 * 8 + j) * SG_STRIDE + b0;
            int o2 = (2 * 8 + j) * SG_STRIDE + b0;
            int o3 = (3 * 8 + j) * SG_STRIDE + b0;
            float gi = p0[o0] + p1[o0] + p2[o0] + p3[o0] + xp[0] + bi0;
            float gf = p0[o1] + p1[o1] + p2[o1] + p3[o1] + xp[1] + bi1;
            float gg = p0[o2] + p1[o2] + p2[o2] + p3[o2] + xp[2] + bi2;
            float go = p0[o3] + p1[o3] + p2[o3] + p3[o3] + xp[3] + bi3;

            float iv = 1.0f / (1.0f + expf(-gi));
            float fv = 1.0f / (1.0f + expf(-gf));
            float gv = tanhf(gg);
            float ov = 1.0f / (1.0f + expf(-go));

            creg = fv * creg + iv * gv;
            float hv = ov * tanhf(creg);
            out[((size_t)b0 * S + t) * H + hid] = hv;
            hnext[hpack_addr(b0, hid)] = f2tf32(hv);

            // Prefetch next step's xproj (hides under barrier spin)
            if (t + 1 < S) {
                size_t xb = ((size_t)b0 * S + (t + 1)) * G + hid;
                xp[0] = __ldg(&g_xproj[xb]);
                xp[1] = __ldg(&g_xproj[xb + H]);
                xp[2] = __ldg(&g_xproj[xb + 2 * H]);
                xp[3] = __ldg(&g_xproj[xb + 3 * H]);
            }
        }

        // Device-wide step barrier (R7-proven form)
        __threadfence();
        __syncthreads();
        if (tid == 0) {
            atomicAdd(barp, 1u);
            unsigned target = (unsigned)(NCTA * (t + 1));
            while (atomicAdd(barp, 0u) < target) {
                __nanosleep(32);
            }
            __threadfence();
        }
        __syncthreads();
    }

    if (pw) g_c[b0 * H + hid] = creg;
}

// ---------------------------------------------------------------------------
// Finalize: hn = out[:, S-1, :], cn = g_c
// ---------------------------------------------------------------------------
__global__ void finalize(float* __restrict__ out) {
    int i = blockIdx.x * blockDim.x + threadIdx.x;
    if (i < B * H) {
        int b = i >> 10, hid = i & 1023;
        size_t tail = (size_t)B * S * H;
        out[tail + i] = out[((size_t)b * S + (S - 1)) * H + hid];
        out[tail + (size_t)B * H + i] = g_c[i];
    }
}

// ---------------------------------------------------------------------------
// Launch
// ---------------------------------------------------------------------------
extern "C" void kernel_launch(void* const* d_in, const int* in_sizes, int n_in,
                              void* d_out, int out_size) {
    (void)in_sizes; (void)n_in; (void)out_size;

    const float* inputs = (const float*)d_in[0];  // [B, S, D]
    const float* h0     = (const float*)d_in[1];  // [1, B, H]
    const float* c0     = (const float*)d_in[2];  // [1, B, H]
    const float* wih    = (const float*)d_in[3];  // [4H, D]
    const float* whh    = (const float*)d_in[4];  // [4H, H]
    const float* bih    = (const float*)d_in[5];  // [4H]
    const float* bhh    = (const float*)d_in[6];  // [4H]
    float* out = (float*)d_out;

    cudaFuncSetAttribute(lstm_persist,
                         cudaFuncAttributeMaxDynamicSharedMemorySize,
                         DYN_SMEM_BYTES);
    cudaFuncSetAttribute(xproj_mma,
                         cudaFuncAttributeMaxDynamicSharedMemorySize,
                         XP_SMEM_BYTES);

    init_state<<<(B * H + 255) / 256, 256>>>(h0, c0);
    prep_wpack<<<(G * H) / 256, 256>>>(whh);
    prep_xpack<<<(B * S * D) / 256, 256>>>(inputs);
    prep_wihpack<<<(G * D) / 256, 256>>>(wih);

    dim3 gx(XP_NNT, XP_NMT);  // 32 x 256
    xproj_mma<<<gx, 256, XP_SMEM_BYTES>>>(bih);

    lstm_persist<<<NCTA, THREADS, DYN_SMEM_BYTES>>>(bhh, out);

    finalize<<<(B * H + 255) / 256, 256>>>(out);
}

// round 12
// speedup vs baseline: 1.0244x; 1.0244x over previous
#include <cuda_runtime.h>
#include <math.h>
#include <stdint.h>

// Problem constants
#define B 64
#define S 512
#define D 1024
#define H 1024
#define G 4096  // 4*H

// Persistent step kernel: 128 CTAs x 512 threads (16 warps, split-k by 2)
#define NCTA 128
#define THREADS 512
// Weight slab per CTA: 128 ksteps * 2 mblk * 32 lanes * 16B = 8192 uint4 = 128KB
#define W_SLAB_UINT4 8192
#define SG_STRIDE 66
#define DYN_SMEM_BYTES (W_SLAB_UINT4 * 16 + 2 * 32 * SG_STRIDE * 4)  // 147968

// xproj tensor-core GEMM geometry
#define XP_BM 128
#define XP_BN 128
#define XP_NMT (B * S / XP_BM)   // 256 m-tiles
#define XP_NNT (G / XP_BN)       // 32 n-tiles
#define XP_CHUNK_U4 1024         // one BK=32 chunk = 16KB
#define XP_SMEM_BYTES (4 * XP_CHUNK_U4 * 16)  // 64KB

// Device scratch (no allocation allowed)
__device__ float    g_xproj[(size_t)B * S * G];                  // [B*S, 4H]
__device__ uint32_t g_wpack[(size_t)NCTA * W_SLAB_UINT4 * 4];    // Whh tf32, fragment-packed
__device__ uint32_t g_hpack[2][128 * 4 * 32 * 4];                // h tf32, fragment-packed (ping-pong)
__device__ float    g_c[B * H];                                  // cell state (start/end only)
__device__ unsigned g_bar;                                       // global step barrier
__device__ uint32_t g_xpack[(size_t)XP_NMT * 128 * 8 * 32 * 4];  // inputs tf32 A-frag-packed
__device__ uint32_t g_wihpack[(size_t)XP_NNT * 128 * 8 * 32 * 4]; // Wih tf32 B-frag-packed

// ---------------------------------------------------------------------------
// Helpers
// ---------------------------------------------------------------------------
__device__ __forceinline__ uint32_t smem_u32(const void* p) {
    uint32_t a;
    asm("{ .reg .u64 t; cvta.to.shared.u64 t, %1; cvt.u32.u64 %0, t; }"
        : "=r"(a) : "l"(p));
    return a;
}

__device__ __forceinline__ uint32_t f2tf32(float f) {
    uint32_t r;
    asm("cvt.rna.tf32.f32 %0, %1;" : "=r"(r) : "f"(f));
    return r;
}

#define CP_ASYNC16(dst, src) \
    asm volatile("cp.async.cg.shared.global [%0], [%1], 16;" :: "r"(dst), "l"(src) : "memory")
#define CP_COMMIT() asm volatile("cp.async.commit_group;" ::: "memory")
#define CP_WAIT(n)  asm volatile("cp.async.wait_group %0;" :: "n"(n) : "memory")

#define MMA_TF32(c0, c1, c2, c3, a0, a1, a2, a3, b0, b1)                     \
    asm volatile("mma.sync.aligned.m16n8k8.row.col.f32.tf32.tf32.f32 "       \
                 "{%0,%1,%2,%3}, {%4,%5,%6,%7}, {%8,%9}, {%0,%1,%2,%3};"     \
                 : "+f"(c0), "+f"(c1), "+f"(c2), "+f"(c3)                    \
                 : "r"(a0), "r"(a1), "r"(a2), "r"(a3), "r"(b0), "r"(b1))

// ---------------------------------------------------------------------------
// Whh prep: tf32 per-lane A-fragment order for the step kernel.
// ---------------------------------------------------------------------------
__global__ void prep_wpack(const float* __restrict__ whh) {
    int idx = blockIdx.x * 256 + threadIdx.x;   // 0 .. 4M-1
    int a     = idx & 3;
    int lane  = (idx >> 2) & 31;
    int mblk  = (idx >> 7) & 1;
    int kstep = (idx >> 8) & 127;
    int ct    = idx >> 15;

    int row16 = (lane >> 2) + 8 * (a & 1);
    int kofs  = (lane & 3) + 4 * (a >> 1);
    int r = mblk * 16 + row16;
    int q = r >> 3;
    int j = r & 7;
    int grow = q * H + ct * 8 + j;
    int k = kstep * 8 + kofs;
    g_wpack[idx] = f2tf32(whh[(size_t)grow * H + k]);
}

// ---------------------------------------------------------------------------
// xproj A-pack: inputs [B*S, D] fp32 -> tf32 A-fragment order.
// ---------------------------------------------------------------------------
__global__ void prep_xpack(const float* __restrict__ inp) {
    int idx = blockIdx.x * 256 + threadIdx.x;   // 0 .. 32M-1
    int a     = idx & 3;
    int lane  = (idx >> 2) & 31;
    int mblk  = (idx >> 7) & 7;
    int kstep = (idx >> 10) & 127;
    int mtile = idx >> 17;

    int m = mtile * 128 + mblk * 16 + (lane >> 2) + 8 * (a & 1);
    int k = kstep * 8 + (lane & 3) + 4 * (a >> 1);
    g_xpack[idx] = f2tf32(inp[(size_t)m * D + k]);
}

// ---------------------------------------------------------------------------
// xproj B-pack: Wih [G, D] fp32 -> tf32 B-fragment order (paired n8 blocks).
// ---------------------------------------------------------------------------
__global__ void prep_wihpack(const float* __restrict__ wih) {
    int idx = blockIdx.x * 256 + threadIdx.x;   // 0 .. 4M-1
    int w     = idx & 3;
    int lane  = (idx >> 2) & 31;
    int npair = (idx >> 7) & 7;
    int kstep = (idx >> 10) & 127;
    int ntile = idx >> 17;

    int nsub = w >> 1, bsel = w & 1;
    int n = ntile * 128 + npair * 16 + nsub * 8 + (lane >> 2);
    int k = kstep * 8 + (lane & 3) + 4 * bsel;
    g_wihpack[idx] = f2tf32(wih[(size_t)n * D + k]);
}

// ---------------------------------------------------------------------------
// hpack addressing
// ---------------------------------------------------------------------------
__device__ __forceinline__ uint32_t hpack_addr(int b, int hid) {
    int kstep = hid >> 3, kk = hid & 7;
    int khalf = kk >> 2, kfrac = kk & 3;
    int nblk = b >> 4, rem = b & 15;
    int jb = rem >> 3, trow = rem & 7;
    int lane = trow * 4 + kfrac;
    int f = khalf * 2 + jb;
    return (uint32_t)(((kstep * 4 + nblk) * 32 + lane) * 4 + f);
}

__global__ void init_state(const float* __restrict__ h0,
                           const float* __restrict__ c0) {
    int i = blockIdx.x * blockDim.x + threadIdx.x;
    if (i == 0) g_bar = 0u;
    if (i < B * H) {
        g_c[i] = c0[i];
        int b = i >> 10, hid = i & 1023;
        g_hpack[0][hpack_addr(b, hid)] = f2tf32(h0[i]);
    }
}

// ---------------------------------------------------------------------------
// xproj GEMM on tensor cores (unchanged from round 7)
// ---------------------------------------------------------------------------
__global__ void __launch_bounds__(256, 2)
xproj_mma(const float* __restrict__ bias) {
    extern __shared__ __align__(16) uint4 xsm[];
    uint32_t aAddr[2] = { smem_u32(xsm), smem_u32(xsm + XP_CHUNK_U4) };
    uint32_t bAddr[2] = { smem_u32(xsm + 2 * XP_CHUNK_U4), smem_u32(xsm + 3 * XP_CHUNK_U4) };

    int tid = threadIdx.x;
    int wid = tid >> 5;
    int lane = tid & 31;
    int wm = wid & 1;
    int wn = wid >> 1;
    int mtile = blockIdx.y;
    int ntile = blockIdx.x;

    const uint4* gA = (const uint4*)g_xpack + (size_t)mtile * (128 * 8 * 32);
    const uint4* gB = (const uint4*)g_wihpack + (size_t)ntile * (128 * 8 * 32);

    float acc[4][4][4] = {};

#pragma unroll
    for (int i = 0; i < 4; i++) {
        int l = tid + i * 256;
        CP_ASYNC16(aAddr[0] + l * 16, (const char*)gA + l * 16);
        CP_ASYNC16(bAddr[0] + l * 16, (const char*)gB + l * 16);
    }
    CP_COMMIT();

    for (int ki = 0; ki < 32; ki++) {
        if (ki + 1 < 32) {
            int nb = (ki + 1) & 1;
            const char* srcA = (const char*)(gA + (size_t)(ki + 1) * XP_CHUNK_U4);
            const char* srcB = (const char*)(gB + (size_t)(ki + 1) * XP_CHUNK_U4);
#pragma unroll
            for (int i = 0; i < 4; i++) {
                int l = tid + i * 256;
                CP_ASYNC16(aAddr[nb] + l * 16, srcA + l * 16);
                CP_ASYNC16(bAddr[nb] + l * 16, srcB + l * 16);
            }
            CP_COMMIT();
            CP_WAIT(1);
        } else {
            CP_WAIT(0);
        }
        __syncthreads();

        const uint4* cA = xsm + (ki & 1) * XP_CHUNK_U4;
        const uint4* cB = xsm + (2 + (ki & 1)) * XP_CHUNK_U4;
#pragma unroll
        for (int ks = 0; ks < 4; ks++) {
            uint4 av[4], bv[2];
#pragma unroll
            for (int m = 0; m < 4; m++)
                av[m] = cA[ks * 256 + (wm * 4 + m) * 32 + lane];
#pragma unroll
            for (int p = 0; p < 2; p++)
                bv[p] = cB[ks * 256 + (wn * 2 + p) * 32 + lane];
#pragma unroll
            for (int m = 0; m < 4; m++) {
                MMA_TF32(acc[m][0][0], acc[m][0][1], acc[m][0][2], acc[m][0][3],
                         av[m].x, av[m].y, av[m].z, av[m].w, bv[0].x, bv[0].y);
                MMA_TF32(acc[m][1][0], acc[m][1][1], acc[m][1][2], acc[m][1][3],
                         av[m].x, av[m].y, av[m].z, av[m].w, bv[0].z, bv[0].w);
                MMA_TF32(acc[m][2][0], acc[m][2][1], acc[m][2][2], acc[m][2][3],
                         av[m].x, av[m].y, av[m].z, av[m].w, bv[1].x, bv[1].y);
                MMA_TF32(acc[m][3][0], acc[m][3][1], acc[m][3][2], acc[m][3][3],
                         av[m].x, av[m].y, av[m].z, av[m].w, bv[1].z, bv[1].w);
            }
        }
        __syncthreads();
    }

#pragma unroll
    for (int m = 0; m < 4; m++) {
        int row = mtile * 128 + wm * 64 + m * 16 + (lane >> 2);
#pragma unroll
        for (int j = 0; j < 4; j++) {
            int col = ntile * 128 + wn * 32 + j * 8 + (lane & 3) * 2;
            float b0 = bias[col], b1 = bias[col + 1];
            *(float2*)&g_xproj[(size_t)row * G + col] =
                make_float2(acc[m][j][0] + b0, acc[m][j][1] + b1);
            *(float2*)&g_xproj[(size_t)(row + 8) * G + col] =
                make_float2(acc[m][j][2] + b0, acc[m][j][3] + b1);
        }
    }
}

// ---------------------------------------------------------------------------
// Persistent LSTM. Round-12: R10 structure (512 threads, split-k by 2 — the
// measured best) with DEEPER ldcg prefetch: 8-kstep double buffer (16
// outstanding uint4 loads/warp, as in R7) instead of 4+4. Combines the two
// independently-verified wins: more warps/SMSP AND enough MLP to cover the
// ~240-380cyc L2 latency.
// ---------------------------------------------------------------------------
__global__ void __launch_bounds__(THREADS, 1)
lstm_persist(const float* __restrict__ bias_hh, float* __restrict__ out) {
    extern __shared__ __align__(16) uint4 smem4[];
    uint4* sW = smem4;                              // 8192 uint4 weight slab
    float* sG = (float*)(smem4 + W_SLAB_UINT4);     // [2][32][SG_STRIDE]

    int tid = threadIdx.x;
    int wid = tid >> 5;
    int lane = tid & 31;
    int bx = blockIdx.x;
    int khalf = wid >> 3;          // 0..1
    int sub = wid & 7;
    int mblk = sub & 1;
    int nblk = sub >> 1;

    const uint4* gW = (const uint4*)g_wpack + (size_t)bx * W_SLAB_UINT4;
#pragma unroll
    for (int i = 0; i < W_SLAB_UINT4 / THREADS; i++)
        sW[tid + i * THREADS] = gW[tid + i * THREADS];

    // Pointwise mapping: thread owns exactly (b, hid), b = tid>>3 (0..63)
    int j = tid & 7;
    int b0 = tid >> 3;
    int hid = bx * 8 + j;
    float bi0 = bias_hh[hid];
    float bi1 = bias_hh[H + hid];
    float bi2 = bias_hh[2 * H + hid];
    float bi3 = bias_hh[3 * H + hid];
    float creg = g_c[b0 * H + hid];

    __syncthreads();

    int bIdx = nblk * 32 + lane;
    int aBase = mblk * 32 + lane;
    int kbase = khalf * 64;
    unsigned* barp = &g_bar;

    // Prefetch xproj for t=0
    float xp[4];
    {
        size_t xb = (size_t)b0 * S * G + hid;
        xp[0] = __ldg(&g_xproj[xb]);
        xp[1] = __ldg(&g_xproj[xb + H]);
        xp[2] = __ldg(&g_xproj[xb + 2 * H]);
        xp[3] = __ldg(&g_xproj[xb + 3 * H]);
    }

    for (int t = 0; t < S; t++) {
        const uint4* gB4 = (const uint4*)g_hpack[t & 1];

        float c00 = 0.f, c01 = 0.f, c02 = 0.f, c03 = 0.f;
        float c10 = 0.f, c11 = 0.f, c12 = 0.f, c13 = 0.f;

        // Deep double-buffer: 8-kstep batches, 16 outstanding loads
        uint4 bvA[8], bvB[8];
#pragma unroll
        for (int k = 0; k < 8; k++)
            bvA[k] = __ldcg(&gB4[(kbase + k) * 128 + bIdx]);

#pragma unroll 1
        for (int ks0 = 0; ks0 < 64; ks0 += 16) {
#pragma unroll
            for (int k = 0; k < 8; k++)
                bvB[k] = __ldcg(&gB4[(kbase + ks0 + 8 + k) * 128 + bIdx]);
#pragma unroll
            for (int k = 0; k < 8; k++) {
                uint4 av = sW[(kbase + ks0 + k) * 64 + aBase];
                MMA_TF32(c00, c01, c02, c03, av.x, av.y, av.z, av.w, bvA[k].x, bvA[k].z);
                MMA_TF32(c10, c11, c12, c13, av.x, av.y, av.z, av.w, bvA[k].y, bvA[k].w);
            }
            if (ks0 + 16 < 64) {
#pragma unroll
                for (int k = 0; k < 8; k++)
                    bvA[k] = __ldcg(&gB4[(kbase + ks0 + 16 + k) * 128 + bIdx]);
            }
#pragma unroll
            for (int k = 0; k < 8; k++) {
                uint4 av = sW[(kbase + ks0 + 8 + k) * 64 + aBase];
                MMA_TF32(c00, c01, c02, c03, av.x, av.y, av.z, av.w, bvB[k].x, bvB[k].z);
                MMA_TF32(c10, c11, c12, c13, av.x, av.y, av.z, av.w, bvB[k].y, bvB[k].w);
            }
        }

        // Exchange: warp writes its partial C into its khalf plane
        {
            float* sGp = sG + khalf * 32 * SG_STRIDE;
            int r0 = mblk * 16 + (lane >> 2);
            int col = nblk * 16 + (lane & 3) * 2;
            *(float2*)&sGp[r0 * SG_STRIDE + col]           = make_float2(c00, c01);
            *(float2*)&sGp[(r0 + 8) * SG_STRIDE + col]     = make_float2(c02, c03);
            *(float2*)&sGp[r0 * SG_STRIDE + col + 8]       = make_float2(c10, c11);
            *(float2*)&sGp[(r0 + 8) * SG_STRIDE + col + 8] = make_float2(c12, c13);
        }
        __syncthreads();

        uint32_t* hnext = g_hpack[(t + 1) & 1];
        {
            const float* p0 = sG;
            const float* p1 = sG + 32 * SG_STRIDE;
            int o0 = (0 * 8 + j) * SG_STRIDE + b0;
            int o1 = (1 * 8 + j) * SG_STRIDE + b0;
            int o2 = (2 * 8 + j) * SG_STRIDE + b0;
            int o3 = (3 * 8 + j) * SG_STRIDE + b0;
            float gi = p0[o0] + p1[o0] + xp[0] + bi0;
            float gf = p0[o1] + p1[o1] + xp[1] + bi1;
            float gg = p0[o2] + p1[o2] + xp[2] + bi2;
            float go = p0[o3] + p1[o3] + xp[3] + bi3;

            float iv = 1.0f / (1.0f + expf(-gi));
            float fv = 1.0f / (1.0f + expf(-gf));
            float gv = tanhf(gg);
            float ov = 1.0f / (1.0f + expf(-go));

            creg = fv * creg + iv * gv;
            float hv = ov * tanhf(creg);
            out[((size_t)b0 * S + t) * H + hid] = hv;
            hnext[hpack_addr(b0, hid)] = f2tf32(hv);
        }

        // Prefetch next step's xproj (hides under barrier spin)
        if (t + 1 < S) {
            size_t xb = ((size_t)b0 * S + (t + 1)) * G + hid;
            xp[0] = __ldg(&g_xproj[xb]);
            xp[1] = __ldg(&g_xproj[xb + H]);
            xp[2] = __ldg(&g_xproj[xb + 2 * H]);
            xp[3] = __ldg(&g_xproj[xb + 3 * H]);
        }

        // Device-wide step barrier (R7-proven form)
        __threadfence();
        __syncthreads();
        if (tid == 0) {
            atomicAdd(barp, 1u);
            unsigned target = (unsigned)(NCTA * (t + 1));
            while (atomicAdd(barp, 0u) < target) {
                __nanosleep(32);
            }
            __threadfence();
        }
        __syncthreads();
    }

    g_c[b0 * H + hid] = creg;
}

// ---------------------------------------------------------------------------
// Finalize: hn = out[:, S-1, :], cn = g_c
// ---------------------------------------------------------------------------
__global__ void finalize(float* __restrict__ out) {
    int i = blockIdx.x * blockDim.x + threadIdx.x;
    if (i < B * H) {
        int b = i >> 10, hid = i & 1023;
        size_t tail = (size_t)B * S * H;
        out[tail + i] = out[((size_t)b * S + (S - 1)) * H + hid];
        out[tail + (size_t)B * H + i] = g_c[i];
    }
}

// ---------------------------------------------------------------------------
// Launch
// ---------------------------------------------------------------------------
extern "C" void kernel_launch(void* const* d_in, const int* in_sizes, int n_in,
                              void* d_out, int out_size) {
    (void)in_sizes; (void)n_in; (void)out_size;

    const float* inputs = (const float*)d_in[0];  // [B, S, D]
    const float* h0     = (const float*)d_in[1];  // [1, B, H]
    const float* c0     = (const float*)d_in[2];  // [1, B, H]
    const float* wih    = (const float*)d_in[3];  // [4H, D]
    const float* whh    = (const float*)d_in[4];  // [4H, H]
    const float* bih    = (const float*)d_in[5];  // [4H]
    const float* bhh    = (const float*)d_in[6];  // [4H]
    float* out = (float*)d_out;

    cudaFuncSetAttribute(lstm_persist,
                         cudaFuncAttributeMaxDynamicSharedMemorySize,
                         DYN_SMEM_BYTES);
    cudaFuncSetAttribute(xproj_mma,
                         cudaFuncAttributeMaxDynamicSharedMemorySize,
                         XP_SMEM_BYTES);

    init_state<<<(B * H + 255) / 256, 256>>>(h0, c0);
    prep_wpack<<<(G * H) / 256, 256>>>(whh);
    prep_xpack<<<(B * S * D) / 256, 256>>>(inputs);
    prep_wihpack<<<(G * D) / 256, 256>>>(wih);

    dim3 gx(XP_NNT, XP_NMT);  // 32 x 256
    xproj_mma<<<gx, 256, XP_SMEM_BYTES>>>(bih);

    lstm_persist<<<NCTA, THREADS, DYN_SMEM_BYTES>>>(bhh, out);

    finalize<<<(B * H + 255) / 256, 256>>>(out);
}

// round 13
// speedup vs baseline: 1.1005x; 1.0743x over previous
#include <cuda_runtime.h>
#include <math.h>
#include <stdint.h>

// Problem constants
#define B 64
#define S 512
#define D 1024
#define H 1024
#define G 4096  // 4*H

// Persistent step kernel: 128 CTAs x 512 threads.
// 16 warps: warp = (kq 0..3, nblk 0..3). Each warp: m32 (both mblks) x n16,
// 32 ksteps. B fragments loaded ONCE per warp and reused across both mblks
// -> issued L2 B-traffic halves vs R10 (512KB -> 256KB per CTA per step).
#define NCTA 128
#define THREADS 512
// Weight slab per CTA: 128 ksteps * 2 mblk * 32 lanes * 16B = 8192 uint4 = 128KB
#define W_SLAB_UINT4 8192
#define SG_STRIDE 66
#define DYN_SMEM_BYTES (W_SLAB_UINT4 * 16 + 4 * 32 * SG_STRIDE * 4)  // 164864

// xproj tensor-core GEMM geometry
#define XP_BM 128
#define XP_BN 128
#define XP_NMT (B * S / XP_BM)   // 256 m-tiles
#define XP_NNT (G / XP_BN)       // 32 n-tiles
#define XP_CHUNK_U4 1024         // one BK=32 chunk = 16KB
#define XP_SMEM_BYTES (4 * XP_CHUNK_U4 * 16)  // 64KB

// Device scratch (no allocation allowed)
__device__ float    g_xproj[(size_t)B * S * G];                  // [B*S, 4H]
__device__ uint32_t g_wpack[(size_t)NCTA * W_SLAB_UINT4 * 4];    // Whh tf32, fragment-packed
__device__ uint32_t g_hpack[2][128 * 4 * 32 * 4];                // h tf32, fragment-packed (ping-pong)
__device__ float    g_c[B * H];                                  // cell state (start/end only)
__device__ unsigned g_bar;                                       // global step barrier
__device__ uint32_t g_xpack[(size_t)XP_NMT * 128 * 8 * 32 * 4];  // inputs tf32 A-frag-packed
__device__ uint32_t g_wihpack[(size_t)XP_NNT * 128 * 8 * 32 * 4]; // Wih tf32 B-frag-packed

// ---------------------------------------------------------------------------
// Helpers
// ---------------------------------------------------------------------------
__device__ __forceinline__ uint32_t smem_u32(const void* p) {
    uint32_t a;
    asm("{ .reg .u64 t; cvta.to.shared.u64 t, %1; cvt.u32.u64 %0, t; }"
        : "=r"(a) : "l"(p));
    return a;
}

__device__ __forceinline__ uint32_t f2tf32(float f) {
    uint32_t r;
    asm("cvt.rna.tf32.f32 %0, %1;" : "=r"(r) : "f"(f));
    return r;
}

#define CP_ASYNC16(dst, src) \
    asm volatile("cp.async.cg.shared.global [%0], [%1], 16;" :: "r"(dst), "l"(src) : "memory")
#define CP_COMMIT() asm volatile("cp.async.commit_group;" ::: "memory")
#define CP_WAIT(n)  asm volatile("cp.async.wait_group %0;" :: "n"(n) : "memory")

#define MMA_TF32(c0, c1, c2, c3, a0, a1, a2, a3, b0, b1)                     \
    asm volatile("mma.sync.aligned.m16n8k8.row.col.f32.tf32.tf32.f32 "       \
                 "{%0,%1,%2,%3}, {%4,%5,%6,%7}, {%8,%9}, {%0,%1,%2,%3};"     \
                 : "+f"(c0), "+f"(c1), "+f"(c2), "+f"(c3)                    \
                 : "r"(a0), "r"(a1), "r"(a2), "r"(a3), "r"(b0), "r"(b1))

// ---------------------------------------------------------------------------
// Whh prep: tf32 per-lane A-fragment order for the step kernel.
// ---------------------------------------------------------------------------
__global__ void prep_wpack(const float* __restrict__ whh) {
    int idx = blockIdx.x * 256 + threadIdx.x;   // 0 .. 4M-1
    int a     = idx & 3;
    int lane  = (idx >> 2) & 31;
    int mblk  = (idx >> 7) & 1;
    int kstep = (idx >> 8) & 127;
    int ct    = idx >> 15;

    int row16 = (lane >> 2) + 8 * (a & 1);
    int kofs  = (lane & 3) + 4 * (a >> 1);
    int r = mblk * 16 + row16;
    int q = r >> 3;
    int j = r & 7;
    int grow = q * H + ct * 8 + j;
    int k = kstep * 8 + kofs;
    g_wpack[idx] = f2tf32(whh[(size_t)grow * H + k]);
}

// ---------------------------------------------------------------------------
// xproj A-pack: inputs [B*S, D] fp32 -> tf32 A-fragment order.
// ---------------------------------------------------------------------------
__global__ void prep_xpack(const float* __restrict__ inp) {
    int idx = blockIdx.x * 256 + threadIdx.x;   // 0 .. 32M-1
    int a     = idx & 3;
    int lane  = (idx >> 2) & 31;
    int mblk  = (idx >> 7) & 7;
    int kstep = (idx >> 10) & 127;
    int mtile = idx >> 17;

    int m = mtile * 128 + mblk * 16 + (lane >> 2) + 8 * (a & 1);
    int k = kstep * 8 + (lane & 3) + 4 * (a >> 1);
    g_xpack[idx] = f2tf32(inp[(size_t)m * D + k]);
}

// ---------------------------------------------------------------------------
// xproj B-pack: Wih [G, D] fp32 -> tf32 B-fragment order (paired n8 blocks).
// ---------------------------------------------------------------------------
__global__ void prep_wihpack(const float* __restrict__ wih) {
    int idx = blockIdx.x * 256 + threadIdx.x;   // 0 .. 4M-1
    int w     = idx & 3;
    int lane  = (idx >> 2) & 31;
    int npair = (idx >> 7) & 7;
    int kstep = (idx >> 10) & 127;
    int ntile = idx >> 17;

    int nsub = w >> 1, bsel = w & 1;
    int n = ntile * 128 + npair * 16 + nsub * 8 + (lane >> 2);
    int k = kstep * 8 + (lane & 3) + 4 * bsel;
    g_wihpack[idx] = f2tf32(wih[(size_t)n * D + k]);
}

// ---------------------------------------------------------------------------
// hpack addressing
// ---------------------------------------------------------------------------
__device__ __forceinline__ uint32_t hpack_addr(int b, int hid) {
    int kstep = hid >> 3, kk = hid & 7;
    int khalf = kk >> 2, kfrac = kk & 3;
    int nblk = b >> 4, rem = b & 15;
    int jb = rem >> 3, trow = rem & 7;
    int lane = trow * 4 + kfrac;
    int f = khalf * 2 + jb;
    return (uint32_t)(((kstep * 4 + nblk) * 32 + lane) * 4 + f);
}

__global__ void init_state(const float* __restrict__ h0,
                           const float* __restrict__ c0) {
    int i = blockIdx.x * blockDim.x + threadIdx.x;
    if (i == 0) g_bar = 0u;
    if (i < B * H) {
        g_c[i] = c0[i];
        int b = i >> 10, hid = i & 1023;
        g_hpack[0][hpack_addr(b, hid)] = f2tf32(h0[i]);
    }
}

// ---------------------------------------------------------------------------
// xproj GEMM on tensor cores (unchanged from round 7)
// ---------------------------------------------------------------------------
__global__ void __launch_bounds__(256, 2)
xproj_mma(const float* __restrict__ bias) {
    extern __shared__ __align__(16) uint4 xsm[];
    uint32_t aAddr[2] = { smem_u32(xsm), smem_u32(xsm + XP_CHUNK_U4) };
    uint32_t bAddr[2] = { smem_u32(xsm + 2 * XP_CHUNK_U4), smem_u32(xsm + 3 * XP_CHUNK_U4) };

    int tid = threadIdx.x;
    int wid = tid >> 5;
    int lane = tid & 31;
    int wm = wid & 1;
    int wn = wid >> 1;
    int mtile = blockIdx.y;
    int ntile = blockIdx.x;

    const uint4* gA = (const uint4*)g_xpack + (size_t)mtile * (128 * 8 * 32);
    const uint4* gB = (const uint4*)g_wihpack + (size_t)ntile * (128 * 8 * 32);

    float acc[4][4][4] = {};

#pragma unroll
    for (int i = 0; i < 4; i++) {
        int l = tid + i * 256;
        CP_ASYNC16(aAddr[0] + l * 16, (const char*)gA + l * 16);
        CP_ASYNC16(bAddr[0] + l * 16, (const char*)gB + l * 16);
    }
    CP_COMMIT();

    for (int ki = 0; ki < 32; ki++) {
        if (ki + 1 < 32) {
            int nb = (ki + 1) & 1;
            const char* srcA = (const char*)(gA + (size_t)(ki + 1) * XP_CHUNK_U4);
            const char* srcB = (const char*)(gB + (size_t)(ki + 1) * XP_CHUNK_U4);
#pragma unroll
            for (int i = 0; i < 4; i++) {
                int l = tid + i * 256;
                CP_ASYNC16(aAddr[nb] + l * 16, srcA + l * 16);
                CP_ASYNC16(bAddr[nb] + l * 16, srcB + l * 16);
            }
            CP_COMMIT();
            CP_WAIT(1);
        } else {
            CP_WAIT(0);
        }
        __syncthreads();

        const uint4* cA = xsm + (ki & 1) * XP_CHUNK_U4;
        const uint4* cB = xsm + (2 + (ki & 1)) * XP_CHUNK_U4;
#pragma unroll
        for (int ks = 0; ks < 4; ks++) {
            uint4 av[4], bv[2];
#pragma unroll
            for (int m = 0; m < 4; m++)
                av[m] = cA[ks * 256 + (wm * 4 + m) * 32 + lane];
#pragma unroll
            for (int p = 0; p < 2; p++)
                bv[p] = cB[ks * 256 + (wn * 2 + p) * 32 + lane];
#pragma unroll
            for (int m = 0; m < 4; m++) {
                MMA_TF32(acc[m][0][0], acc[m][0][1], acc[m][0][2], acc[m][0][3],
                         av[m].x, av[m].y, av[m].z, av[m].w, bv[0].x, bv[0].y);
                MMA_TF32(acc[m][1][0], acc[m][1][1], acc[m][1][2], acc[m][1][3],
                         av[m].x, av[m].y, av[m].z, av[m].w, bv[0].z, bv[0].w);
                MMA_TF32(acc[m][2][0], acc[m][2][1], acc[m][2][2], acc[m][2][3],
                         av[m].x, av[m].y, av[m].z, av[m].w, bv[1].x, bv[1].y);
                MMA_TF32(acc[m][3][0], acc[m][3][1], acc[m][3][2], acc[m][3][3],
                         av[m].x, av[m].y, av[m].z, av[m].w, bv[1].z, bv[1].w);
            }
        }
        __syncthreads();
    }

#pragma unroll
    for (int m = 0; m < 4; m++) {
        int row = mtile * 128 + wm * 64 + m * 16 + (lane >> 2);
#pragma unroll
        for (int j = 0; j < 4; j++) {
            int col = ntile * 128 + wn * 32 + j * 8 + (lane & 3) * 2;
            float b0 = bias[col], b1 = bias[col + 1];
            *(float2*)&g_xproj[(size_t)row * G + col] =
                make_float2(acc[m][j][0] + b0, acc[m][j][1] + b1);
            *(float2*)&g_xproj[(size_t)(row + 8) * G + col] =
                make_float2(acc[m][j][2] + b0, acc[m][j][3] + b1);
        }
    }
}

// ---------------------------------------------------------------------------
// Persistent LSTM. Round-13: warp = (kq, nblk) covers BOTH mblks (m32 x n16
// per warp, 32 ksteps). Each B fragment is ldcg'd ONCE and reused for both
// A fragments -> issued L2 traffic per CTA per step halves (512KB -> 256KB).
// 16 warps / 512 threads (proven best warp count), depth-4 double buffer.
// ---------------------------------------------------------------------------
__global__ void __launch_bounds__(THREADS, 1)
lstm_persist(const float* __restrict__ bias_hh, float* __restrict__ out) {
    extern __shared__ __align__(16) uint4 smem4[];
    uint4* sW = smem4;                              // 8192 uint4 weight slab
    float* sG = (float*)(smem4 + W_SLAB_UINT4);     // [4][32][SG_STRIDE]

    int tid = threadIdx.x;
    int wid = tid >> 5;
    int lane = tid & 31;
    int bx = blockIdx.x;
    int kq = wid >> 2;             // k-quarter 0..3
    int nblk = wid & 3;            // n-block 0..3

    const uint4* gW = (const uint4*)g_wpack + (size_t)bx * W_SLAB_UINT4;
#pragma unroll
    for (int i = 0; i < W_SLAB_UINT4 / THREADS; i++)
        sW[tid + i * THREADS] = gW[tid + i * THREADS];

    // Pointwise mapping: thread owns exactly (b, hid), b = tid>>3 (0..63)
    int j = tid & 7;
    int b0 = tid >> 3;
    int hid = bx * 8 + j;
    float bi0 = bias_hh[hid];
    float bi1 = bias_hh[H + hid];
    float bi2 = bias_hh[2 * H + hid];
    float bi3 = bias_hh[3 * H + hid];
    float creg = g_c[b0 * H + hid];

    __syncthreads();

    int bIdx = nblk * 32 + lane;
    int kbase = kq * 32;
    unsigned* barp = &g_bar;

    // Prefetch xproj for t=0
    float xp[4];
    {
        size_t xb = (size_t)b0 * S * G + hid;
        xp[0] = __ldg(&g_xproj[xb]);
        xp[1] = __ldg(&g_xproj[xb + H]);
        xp[2] = __ldg(&g_xproj[xb + 2 * H]);
        xp[3] = __ldg(&g_xproj[xb + 3 * H]);
    }

    for (int t = 0; t < S; t++) {
        const uint4* gB4 = (const uint4*)g_hpack[t & 1];

        // acc[mblk][n8frag][4]
        float a000 = 0.f, a001 = 0.f, a002 = 0.f, a003 = 0.f;
        float a010 = 0.f, a011 = 0.f, a012 = 0.f, a013 = 0.f;
        float a100 = 0.f, a101 = 0.f, a102 = 0.f, a103 = 0.f;
        float a110 = 0.f, a111 = 0.f, a112 = 0.f, a113 = 0.f;

        uint4 bvA[4], bvB[4];
#pragma unroll
        for (int k = 0; k < 4; k++)
            bvA[k] = __ldcg(&gB4[(kbase + k) * 128 + bIdx]);

#pragma unroll 1
        for (int ks0 = 0; ks0 < 32; ks0 += 8) {
#pragma unroll
            for (int k = 0; k < 4; k++)
                bvB[k] = __ldcg(&gB4[(kbase + ks0 + 4 + k) * 128 + bIdx]);
#pragma unroll
            for (int k = 0; k < 4; k++) {
                uint4 av0 = sW[(kbase + ks0 + k) * 64 + lane];        // mblk 0
                uint4 av1 = sW[(kbase + ks0 + k) * 64 + 32 + lane];   // mblk 1
                MMA_TF32(a000, a001, a002, a003, av0.x, av0.y, av0.z, av0.w, bvA[k].x, bvA[k].z);
                MMA_TF32(a010, a011, a012, a013, av0.x, av0.y, av0.z, av0.w, bvA[k].y, bvA[k].w);
                MMA_TF32(a100, a101, a102, a103, av1.x, av1.y, av1.z, av1.w, bvA[k].x, bvA[k].z);
                MMA_TF32(a110, a111, a112, a113, av1.x, av1.y, av1.z, av1.w, bvA[k].y, bvA[k].w);
            }
            if (ks0 + 8 < 32) {
#pragma unroll
                for (int k = 0; k < 4; k++)
                    bvA[k] = __ldcg(&gB4[(kbase + ks0 + 8 + k) * 128 + bIdx]);
            }
#pragma unroll
            for (int k = 0; k < 4; k++) {
                uint4 av0 = sW[(kbase + ks0 + 4 + k) * 64 + lane];
                uint4 av1 = sW[(kbase + ks0 + 4 + k) * 64 + 32 + lane];
                MMA_TF32(a000, a001, a002, a003, av0.x, av0.y, av0.z, av0.w, bvB[k].x, bvB[k].z);
                MMA_TF32(a010, a011, a012, a013, av0.x, av0.y, av0.z, av0.w, bvB[k].y, bvB[k].w);
                MMA_TF32(a100, a101, a102, a103, av1.x, av1.y, av1.z, av1.w, bvB[k].x, bvB[k].z);
                MMA_TF32(a110, a111, a112, a113, av1.x, av1.y, av1.z, av1.w, bvB[k].y, bvB[k].w);
            }
        }

        // Exchange: warp writes both mblk partial tiles into its kq plane
        {
            float* sGp = sG + kq * 32 * SG_STRIDE;
            int rr = lane >> 2;
            int col = nblk * 16 + (lane & 3) * 2;
            *(float2*)&sGp[rr * SG_STRIDE + col]            = make_float2(a000, a001);
            *(float2*)&sGp[(rr + 8) * SG_STRIDE + col]      = make_float2(a002, a003);
            *(float2*)&sGp[rr * SG_STRIDE + col + 8]        = make_float2(a010, a011);
            *(float2*)&sGp[(rr + 8) * SG_STRIDE + col + 8]  = make_float2(a012, a013);
            *(float2*)&sGp[(rr + 16) * SG_STRIDE + col]     = make_float2(a100, a101);
            *(float2*)&sGp[(rr + 24) * SG_STRIDE + col]     = make_float2(a102, a103);
            *(float2*)&sGp[(rr + 16) * SG_STRIDE + col + 8] = make_float2(a110, a111);
            *(float2*)&sGp[(rr + 24) * SG_STRIDE + col + 8] = make_float2(a112, a113);
        }
        __syncthreads();

        uint32_t* hnext = g_hpack[(t + 1) & 1];
        {
            const float* p0 = sG;
            const float* p1 = sG + 1 * 32 * SG_STRIDE;
            const float* p2 = sG + 2 * 32 * SG_STRIDE;
            const float* p3 = sG + 3 * 32 * SG_STRIDE;
            int o0 = (0 * 8 + j) * SG_STRIDE + b0;
            int o1 = (1 * 8 + j) * SG_STRIDE + b0;
            int o2 = (2 * 8 + j) * SG_STRIDE + b0;
            int o3 = (3 * 8 + j) * SG_STRIDE + b0;
            float gi = (p0[o0] + p1[o0]) + (p2[o0] + p3[o0]) + xp[0] + bi0;
            float gf = (p0[o1] + p1[o1]) + (p2[o1] + p3[o1]) + xp[1] + bi1;
            float gg = (p0[o2] + p1[o2]) + (p2[o2] + p3[o2]) + xp[2] + bi2;
            float go = (p0[o3] + p1[o3]) + (p2[o3] + p3[o3]) + xp[3] + bi3;

            float iv = 1.0f / (1.0f + expf(-gi));
            float fv = 1.0f / (1.0f + expf(-gf));
            float gv = tanhf(gg);
            float ov = 1.0f / (1.0f + expf(-go));

            creg = fv * creg + iv * gv;
            float hv = ov * tanhf(creg);
            out[((size_t)b0 * S + t) * H + hid] = hv;
            hnext[hpack_addr(b0, hid)] = f2tf32(hv);
        }

        // Prefetch next step's xproj (hides under barrier spin)
        if (t + 1 < S) {
            size_t xb = ((size_t)b0 * S + (t + 1)) * G + hid;
            xp[0] = __ldg(&g_xproj[xb]);
            xp[1] = __ldg(&g_xproj[xb + H]);
            xp[2] = __ldg(&g_xproj[xb + 2 * H]);
            xp[3] = __ldg(&g_xproj[xb + 3 * H]);
        }

        // Device-wide step barrier (R7-proven form)
        __threadfence();
        __syncthreads();
        if (tid == 0) {
            atomicAdd(barp, 1u);
            unsigned target = (unsigned)(NCTA * (t + 1));
            while (atomicAdd(barp, 0u) < target) {
                __nanosleep(32);
            }
            __threadfence();
        }
        __syncthreads();
    }

    g_c[b0 * H + hid] = creg;
}

// ---------------------------------------------------------------------------
// Finalize: hn = out[:, S-1, :], cn = g_c
// ---------------------------------------------------------------------------
__global__ void finalize(float* __restrict__ out) {
    int i = blockIdx.x * blockDim.x + threadIdx.x;
    if (i < B * H) {
        int b = i >> 10, hid = i & 1023;
        size_t tail = (size_t)B * S * H;
        out[tail + i] = out[((size_t)b * S + (S - 1)) * H + hid];
        out[tail + (size_t)B * H + i] = g_c[i];
    }
}

// ---------------------------------------------------------------------------
// Launch
// ---------------------------------------------------------------------------
extern "C" void kernel_launch(void* const* d_in, const int* in_sizes, int n_in,
                              void* d_out, int out_size) {
    (void)in_sizes; (void)n_in; (void)out_size;

    const float* inputs = (const float*)d_in[0];  // [B, S, D]
    const float* h0     = (const float*)d_in[1];  // [1, B, H]
    const float* c0     = (const float*)d_in[2];  // [1, B, H]
    const float* wih    = (const float*)d_in[3];  // [4H, D]
    const float* whh    = (const float*)d_in[4];  // [4H, H]
    const float* bih    = (const float*)d_in[5];  // [4H]
    const float* bhh    = (const float*)d_in[6];  // [4H]
    float* out = (float*)d_out;

    cudaFuncSetAttribute(lstm_persist,
                         cudaFuncAttributeMaxDynamicSharedMemorySize,
                         DYN_SMEM_BYTES);
    cudaFuncSetAttribute(xproj_mma,
                         cudaFuncAttributeMaxDynamicSharedMemorySize,
                         XP_SMEM_BYTES);

    init_state<<<(B * H + 255) / 256, 256>>>(h0, c0);
    prep_wpack<<<(G * H) / 256, 256>>>(whh);
    prep_xpack<<<(B * S * D) / 256, 256>>>(inputs);
    prep_wihpack<<<(G * D) / 256, 256>>>(wih);

    dim3 gx(XP_NNT, XP_NMT);  // 32 x 256
    xproj_mma<<<gx, 256, XP_SMEM_BYTES>>>(bih);

    lstm_persist<<<NCTA, THREADS, DYN_SMEM_BYTES>>>(bhh, out);

    finalize<<<(B * H + 255) / 256, 256>>>(out);
}